// round 4
// baseline (speedup 1.0000x reference)
#include <cuda_runtime.h>
#include <cstdint>
#include <math.h>

// ---------------- problem constants ----------------
#define NB   4
#define SEQ  8192
#define DIM  1024
#define MTOT (NB*SEQ)          // 32768 rows

// ---------------- GEMM tiling ----------------------
#define BM 128
#define BN 128
#define BK 32
#define AS_STR 36              // 128x32 A tile, stride 36 floats (pad -> conflict-free frags)
#define BS_STR 136             // 32x128 B tile, stride 136 floats (pad -> conflict-free frags)
#define SMEM_BYTES ((2*BM*AS_STR + 2*BK*BS_STR)*4)   // 71680 B, double buffered

// ---------------- device scratch (allocation-free rule: __device__ globals) --
__device__ float g_Q[(size_t)MTOT*DIM];   // Q activations, later overwritten with U
__device__ float g_K[(size_t)MTOT*DIM];   // K activations (elu+1)
__device__ float g_V[(size_t)MTOT*DIM];   // V (raw)
__device__ float g_pKV[32][NB*DIM];       // partial sums over s-chunks
__device__ float g_pKs[32][NB*DIM];
__device__ float g_KV[NB*DIM];
__device__ float g_Ks[NB*DIM];

// ---------------- small helpers --------------------
__device__ __forceinline__ void cp_async16(float* smem_dst, const float* gsrc) {
    uint32_t s = (uint32_t)__cvta_generic_to_shared(smem_dst);
    asm volatile("cp.async.cg.shared.global [%0], [%1], 16;\n" :: "r"(s), "l"(gsrc));
}
#define CP_COMMIT() asm volatile("cp.async.commit_group;\n")
#define CP_WAIT(n)  asm volatile("cp.async.wait_group %0;\n" :: "n"(n))

__device__ __forceinline__ uint32_t f2tf(float f) {
    uint32_t u;
    asm("cvt.rna.tf32.f32 %0, %1;" : "=r"(u) : "f"(f));
    return u;
}

__device__ __forceinline__ void mma_tf32(float& d0, float& d1, float& d2, float& d3,
                                         uint32_t a0, uint32_t a1, uint32_t a2, uint32_t a3,
                                         uint32_t b0, uint32_t b1) {
    asm volatile(
        "mma.sync.aligned.m16n8k8.row.col.f32.tf32.tf32.f32 "
        "{%0,%1,%2,%3},{%4,%5,%6,%7},{%8,%9},{%0,%1,%2,%3};\n"
        : "+f"(d0), "+f"(d1), "+f"(d2), "+f"(d3)
        : "r"(a0), "r"(a1), "r"(a2), "r"(a3), "r"(b0), "r"(b1));
}

// 128x128x1024 tile mainloop: A row-major [*,1024], B row-major [1024,*], lda=ldb=1024.
// Warp layout: 8 warps = 2 (M) x 4 (N); warp tile 64x32; mma m16n8k8 tf32.
__device__ __forceinline__ void gemm_tile(const float* __restrict__ A,
                                          const float* __restrict__ B,
                                          int m0, int n0,
                                          float* sA, float* sB,
                                          float acc[4][4][4]) {
    const int tid = threadIdx.x;
    const int NK  = DIM / BK;   // 32 k-tiles

    auto issue = [&](int kt, int buf) {
        // A: 128 rows x 32 cols; thread -> (row tid>>3, 4-float col (tid&7)*4), 4 row-steps of 32
        {
            const float* src = A + (size_t)(m0 + (tid >> 3)) * DIM + kt * BK + ((tid & 7) << 2);
            float* dst = sA + buf * (BM * AS_STR) + (tid >> 3) * AS_STR + ((tid & 7) << 2);
#pragma unroll
            for (int i = 0; i < 4; i++)
                cp_async16(dst + i * 32 * AS_STR, src + (size_t)i * 32 * DIM);
        }
        // B: 32 rows x 128 cols; thread -> (row tid>>5, 4-float col (tid&31)*4), 4 row-steps of 8
        {
            const float* src = B + (size_t)(kt * BK + (tid >> 5)) * DIM + n0 + ((tid & 31) << 2);
            float* dst = sB + buf * (BK * BS_STR) + (tid >> 5) * BS_STR + ((tid & 31) << 2);
#pragma unroll
            for (int i = 0; i < 4; i++)
                cp_async16(dst + i * 8 * BS_STR, src + (size_t)i * 8 * DIM);
        }
        CP_COMMIT();
    };

    issue(0, 0);

    const int warp = tid >> 5, lane = tid & 31;
    const int wm = warp & 1, wn = warp >> 1;
    const int g = lane >> 2, t = lane & 3;

    for (int kt = 0; kt < NK; ++kt) {
        const int buf = kt & 1;
        if (kt + 1 < NK) { issue(kt + 1, buf ^ 1); CP_WAIT(1); }
        else             { CP_WAIT(0); }
        __syncthreads();

        const float* Ab = sA + buf * (BM * AS_STR) + (wm * 64 + g) * AS_STR + t;
        const float* Bb = sB + buf * (BK * BS_STR) + t * BS_STR + wn * 32 + g;

#pragma unroll
        for (int ks = 0; ks < 4; ++ks) {          // 4 x k=8 per BK tile
            uint32_t af[4][4], bf[4][2];
#pragma unroll
            for (int mt = 0; mt < 4; mt++) {
                const float* ap = Ab + mt * 16 * AS_STR + ks * 8;
                af[mt][0] = f2tf(ap[0]);
                af[mt][1] = f2tf(ap[8 * AS_STR]);
                af[mt][2] = f2tf(ap[4]);
                af[mt][3] = f2tf(ap[8 * AS_STR + 4]);
            }
#pragma unroll
            for (int nt = 0; nt < 4; nt++) {
                const float* bp = Bb + ks * 8 * BS_STR + nt * 8;
                bf[nt][0] = f2tf(bp[0]);
                bf[nt][1] = f2tf(bp[4 * BS_STR]);
            }
#pragma unroll
            for (int mt = 0; mt < 4; mt++)
#pragma unroll
                for (int nt = 0; nt < 4; nt++)
                    mma_tf32(acc[mt][nt][0], acc[mt][nt][1], acc[mt][nt][2], acc[mt][nt][3],
                             af[mt][0], af[mt][1], af[mt][2], af[mt][3],
                             bf[nt][0], bf[nt][1]);
        }
        __syncthreads();
    }
}

// ---------------- kernel 1: fused QKV projection + elu+1 on Q,K -------------
__global__ void __launch_bounds__(256, 2)
gemm_qkv(const float* __restrict__ x,
         const float* __restrict__ wq, const float* __restrict__ wk, const float* __restrict__ wv,
         const float* __restrict__ bq, const float* __restrict__ bk, const float* __restrict__ bv) {
    extern __shared__ float smem[];
    float* sA = smem;
    float* sB = smem + 2 * BM * AS_STR;

    const int w  = blockIdx.x >> 3;            // 0:q 1:k 2:v
    const int n0 = (blockIdx.x & 7) * BN;
    const int m0 = blockIdx.y * BM;

    const float* B    = (w == 0) ? wq : (w == 1) ? wk : wv;
    const float* bias = (w == 0) ? bq : (w == 1) ? bk : bv;
    float* outp       = (w == 0) ? g_Q : (w == 1) ? g_K : g_V;
    const bool act = (w < 2);

    float acc[4][4][4] = {};
    gemm_tile(x, B, m0, n0, sA, sB, acc);

    const int warp = threadIdx.x >> 5, lane = threadIdx.x & 31;
    const int wm = warp & 1, wn = warp >> 1;
    const int g = lane >> 2, t = lane & 3;

#pragma unroll
    for (int mt = 0; mt < 4; mt++) {
#pragma unroll
        for (int nt = 0; nt < 4; nt++) {
            const int col  = n0 + wn * 32 + nt * 8 + t * 2;
            const int row0 = m0 + wm * 64 + mt * 16 + g;
            const float b0v = bias[col], b1v = bias[col + 1];
            float v0 = acc[mt][nt][0] + b0v;
            float v1 = acc[mt][nt][1] + b1v;
            float v2 = acc[mt][nt][2] + b0v;
            float v3 = acc[mt][nt][3] + b1v;
            if (act) {  // elu(x)+1 = x+1 (x>0) else exp(x)
                v0 = (v0 > 0.f) ? v0 + 1.f : expf(v0);
                v1 = (v1 > 0.f) ? v1 + 1.f : expf(v1);
                v2 = (v2 > 0.f) ? v2 + 1.f : expf(v2);
                v3 = (v3 > 0.f) ? v3 + 1.f : expf(v3);
            }
            *(float2*)(outp + (size_t)row0 * DIM + col)       = make_float2(v0, v1);
            *(float2*)(outp + (size_t)(row0 + 8) * DIM + col) = make_float2(v2, v3);
        }
    }
}

// ---------------- kernel 2a: partial reductions over s-chunks ---------------
__global__ void reduce_partial() {
    const int h  = blockIdx.x * 128 + threadIdx.x;  // 0..1023
    const int sc = blockIdx.y;                      // 0..31 (256 s each)
    const int n  = blockIdx.z;                      // 0..3
    const size_t base = ((size_t)(n * SEQ + sc * 256)) * DIM + h;
    const float* Kp = g_K + base;
    const float* Vp = g_V + base;
    float kv = 0.f, ks = 0.f;
#pragma unroll 8
    for (int i = 0; i < 256; i++) {
        const float k = Kp[(size_t)i * DIM];
        const float v = Vp[(size_t)i * DIM];
        kv = fmaf(k, v, kv);
        ks += k;
    }
    g_pKV[sc][n * DIM + h] = kv;
    g_pKs[sc][n * DIM + h] = ks;
}

// ---------------- kernel 2b: final reduction --------------------------------
__global__ void reduce_final() {
    const int idx = blockIdx.x * blockDim.x + threadIdx.x;  // 0..4095
    float kv = 0.f, ks = 0.f;
#pragma unroll
    for (int i = 0; i < 32; i++) { kv += g_pKV[i][idx]; ks += g_pKs[i][idx]; }
    g_KV[idx] = kv;
    g_Ks[idx] = ks;
}

// ---------------- kernel 3: U = Q*KV / (Q*Ksum + 1e-6), in place in g_Q -----
__global__ void apply_u() {
    const size_t i4 = (size_t)blockIdx.x * 256 + threadIdx.x;  // over 8M float4
    const size_t f  = i4 * 4;
    const int n = (int)(f >> 23);      // row = f>>10; n = row>>13
    const int h = (int)(f & 1023);
    float4 q  = ((float4*)g_Q)[i4];
    const float4 kv = *(const float4*)(g_KV + n * DIM + h);
    const float4 ks = *(const float4*)(g_Ks + n * DIM + h);
    q.x = q.x * kv.x / fmaf(q.x, ks.x, 1e-6f);
    q.y = q.y * kv.y / fmaf(q.y, ks.y, 1e-6f);
    q.z = q.z * kv.z / fmaf(q.z, ks.z, 1e-6f);
    q.w = q.w * kv.w / fmaf(q.w, ks.w, 1e-6f);
    ((float4*)g_Q)[i4] = q;
}

// ---------------- kernel 4: out = gelu_tanh(U @ wo + bo) --------------------
__device__ __forceinline__ float gelu_tanh(float v) {
    const float c = 0.7978845608028654f;
    return 0.5f * v * (1.f + tanhf(c * (v + 0.044715f * v * v * v)));
}

__global__ void __launch_bounds__(256, 2)
gemm_out(const float* __restrict__ wo, const float* __restrict__ bo,
         float* __restrict__ out) {
    extern __shared__ float smem[];
    float* sA = smem;
    float* sB = smem + 2 * BM * AS_STR;

    const int n0 = blockIdx.x * BN;
    const int m0 = blockIdx.y * BM;

    float acc[4][4][4] = {};
    gemm_tile(g_Q, wo, m0, n0, sA, sB, acc);

    const int warp = threadIdx.x >> 5, lane = threadIdx.x & 31;
    const int wm = warp & 1, wn = warp >> 1;
    const int g = lane >> 2, t = lane & 3;

#pragma unroll
    for (int mt = 0; mt < 4; mt++) {
#pragma unroll
        for (int nt = 0; nt < 4; nt++) {
            const int col  = n0 + wn * 32 + nt * 8 + t * 2;
            const int row0 = m0 + wm * 64 + mt * 16 + g;
            const float b0v = bo[col], b1v = bo[col + 1];
            const float v0 = gelu_tanh(acc[mt][nt][0] + b0v);
            const float v1 = gelu_tanh(acc[mt][nt][1] + b1v);
            const float v2 = gelu_tanh(acc[mt][nt][2] + b0v);
            const float v3 = gelu_tanh(acc[mt][nt][3] + b1v);
            *(float2*)(out + (size_t)row0 * DIM + col)       = make_float2(v0, v1);
            *(float2*)(out + (size_t)(row0 + 8) * DIM + col) = make_float2(v2, v3);
        }
    }
}

// ---------------- launch ----------------------------------------------------
extern "C" void kernel_launch(void* const* d_in, const int* in_sizes, int n_in,
                              void* d_out, int out_size) {
    const float* x  = (const float*)d_in[0];
    const float* wq = (const float*)d_in[1];
    const float* bq = (const float*)d_in[2];
    const float* wk = (const float*)d_in[3];
    const float* bk = (const float*)d_in[4];
    const float* wv = (const float*)d_in[5];
    const float* bv = (const float*)d_in[6];
    const float* wo = (const float*)d_in[7];
    const float* bo = (const float*)d_in[8];
    float* out = (float*)d_out;

    cudaFuncSetAttribute(gemm_qkv, cudaFuncAttributeMaxDynamicSharedMemorySize, SMEM_BYTES);
    cudaFuncSetAttribute(gemm_out, cudaFuncAttributeMaxDynamicSharedMemorySize, SMEM_BYTES);

    // grid.x = (w, n-block) so concurrent CTAs share A rows (L2 reuse of x / U)
    gemm_qkv<<<dim3(24, 256, 1), 256, SMEM_BYTES>>>(x, wq, wk, wv, bq, bk, bv);
    reduce_partial<<<dim3(8, 32, 4), 128>>>();
    reduce_final<<<16, 256>>>();
    apply_u<<<32768, 256>>>();
    gemm_out<<<dim3(8, 256, 1), 256, SMEM_BYTES>>>(wo, bo, out);
}